// round 7
// baseline (speedup 1.0000x reference)
#include <cuda_runtime.h>
#include <cuda_bf16.h>

// x: [32, 256, 32, 16, 16] fp32 -> out: [32, 256, 32, 31, 4] fp32
// Tiles = 32*256*32 = 262144 independent 16x16 (h x w) blocks.
// BIN_NUM = [16,8,4,2,1] (height bins), WIDTH_TOKEN_NUM = 4.
// Output dim-3 offsets: b=16 -> [0,16), b=8 -> [16,24), b=4 -> [24,28),
// b=2 -> [28,30), b=1 -> [30,31).
//
// R5: same compute decomposition as R4 (16 threads/tile: width token t x row
// quarter q; 4 front-batched float4 loads; local pyramid through b=4; shuffle
// combines for b=2 / b=1), but all 124 tokens per tile are staged in SMEM and
// then written to gmem as dense, perfectly-coalesced STG.128 (the block's
// 16-tile output span is 7936 contiguous bytes).

#define N_TILES (32 * 256 * 32)
#define TILES_PER_BLOCK 16
#define OUT_PER_TILE 124
#define OUT_PER_BLOCK (TILES_PER_BLOCK * OUT_PER_TILE)   // 1984 floats = 496 float4

__device__ __forceinline__ float4 f4add(float4 a, float4 b) {
    return make_float4(a.x + b.x, a.y + b.y, a.z + b.z, a.w + b.w);
}
__device__ __forceinline__ float4 f4max(float4 a, float4 b) {
    return make_float4(fmaxf(a.x, b.x), fmaxf(a.y, b.y),
                       fmaxf(a.z, b.z), fmaxf(a.w, b.w));
}
__device__ __forceinline__ float4 f4shfl_xor(float4 a, int m) {
    float4 r;
    r.x = __shfl_xor_sync(0xffffffffu, a.x, m);
    r.y = __shfl_xor_sync(0xffffffffu, a.y, m);
    r.z = __shfl_xor_sync(0xffffffffu, a.z, m);
    r.w = __shfl_xor_sync(0xffffffffu, a.w, m);
    return r;
}
// token from per-column (sum, max): z_c = sum_c * inv + max_c,
// token = mean_c(z) + max_c(z)
__device__ __forceinline__ float token(float4 s, float4 m, float inv) {
    float zx = fmaf(s.x, inv, m.x);
    float zy = fmaf(s.y, inv, m.y);
    float zz = fmaf(s.z, inv, m.z);
    float zw = fmaf(s.w, inv, m.w);
    float mean = ((zx + zy) + (zz + zw)) * 0.25f;
    float mx = fmaxf(fmaxf(zx, zy), fmaxf(zz, zw));
    return mean + mx;
}

__global__ void __launch_bounds__(256, 6)
hwtp_kernel(const float* __restrict__ x, float* __restrict__ out) {
    __shared__ float sout[OUT_PER_BLOCK];   // block's output image, 7936 B

    int tid  = threadIdx.x;
    int t    = tid & 3;            // width token (4 cols)
    int q    = (tid >> 2) & 3;     // row quarter: rows [4q, 4q+4)
    int tl   = tid >> 4;           // tile within block (0..15)
    int tile = blockIdx.x * TILES_PER_BLOCK + tl;

    // float4 view of the tile: 64 float4; row stride = 4 float4.
    const float4* __restrict__ src =
        reinterpret_cast<const float4*>(x + (size_t)tile * 256) + q * 16 + t;
    float* __restrict__ sdst = sout + tl * OUT_PER_TILE + t;

    // ---- Phase 1: all 4 loads up front ----
    float4 v[4];
#pragma unroll
    for (int r = 0; r < 4; ++r) {
        v[r] = src[r * 4];
    }

    // ---- Phase 2: local pyramid (rows 4q .. 4q+3), tokens -> SMEM ----
    float4 s2s, s2m, s4s, s4m;

#pragma unroll
    for (int r = 0; r < 4; ++r) {
        float4 w = v[r];

        // b=16: single-row bins (global row = 4q + r)
        sdst[(q * 4 + r) * 4] = token(w, w, 1.0f);

        if ((r & 1) == 0) {
            s2s = w; s2m = w;
        } else {
            // b=8: 2-row bins (global bin = 2q + (r>>1))
            s2s = f4add(s2s, w);
            s2m = f4max(s2m, w);
            sdst[(16 + q * 2 + (r >> 1)) * 4] = token(s2s, s2m, 0.5f);

            if (r == 1) {
                s4s = s2s; s4m = s2m;
            } else {
                // b=4: 4-row bin (global bin = q)
                s4s = f4add(s4s, s2s);
                s4m = f4max(s4m, s2m);
                sdst[(24 + q) * 4] = token(s4s, s4m, 0.25f);
            }
        }
    }

    // ---- b=2: combine quarter pairs (q with q^1) via lane^4 ----
    float4 s8s = f4add(s4s, f4shfl_xor(s4s, 4));
    float4 s8m = f4max(s4m, f4shfl_xor(s4m, 4));
    if ((q & 1) == 0) {
        sdst[(28 + (q >> 1)) * 4] = token(s8s, s8m, 0.125f);
    }

    // ---- b=1: combine halves (q with q^2) via lane^8 ----
    float4 s16s = f4add(s8s, f4shfl_xor(s8s, 8));
    float4 s16m = f4max(s8m, f4shfl_xor(s8m, 8));
    if (q == 0) {
        sdst[30 * 4] = token(s16s, s16m, 0.0625f);
    }

    __syncthreads();

    // ---- Phase 3: dense coalesced copy-out (496 float4 = 7936 B contiguous) ----
    const float4* __restrict__ s4 = reinterpret_cast<const float4*>(sout);
    float4* __restrict__ g4 =
        reinterpret_cast<float4*>(out + (size_t)blockIdx.x * OUT_PER_BLOCK);

    g4[tid] = s4[tid];                       // float4s [0, 256)
    if (tid < OUT_PER_BLOCK / 4 - 256) {     // float4s [256, 496)
        g4[256 + tid] = s4[256 + tid];
    }
}

extern "C" void kernel_launch(void* const* d_in, const int* in_sizes, int n_in,
                              void* d_out, int out_size) {
    const float* x = (const float*)d_in[0];
    float* out = (float*)d_out;
    // 262144 tiles / 16 tiles-per-block = 16384 blocks of 256 threads (exact)
    hwtp_kernel<<<N_TILES / TILES_PER_BLOCK, 256>>>(x, out);
}

// round 8
// speedup vs baseline: 1.0139x; 1.0139x over previous
#include <cuda_runtime.h>
#include <cuda_bf16.h>

// x: [32, 256, 32, 16, 16] fp32 -> out: [32, 256, 32, 31, 4] fp32
// Tiles = 32*256*32 = 262144 independent 16x16 (h x w) blocks.
// BIN_NUM = [16,8,4,2,1] (height bins), WIDTH_TOKEN_NUM = 4.
// Output dim-3 offsets: b=16 -> [0,16), b=8 -> [16,24), b=4 -> [24,28),
// b=2 -> [28,30), b=1 -> [30,31).
//
// R6: R4 decomposition (16 threads/tile: width token t x row quarter q;
// 4 front-batched float4 loads; local pyramid through b=4; shuffle combines
// for b=2 / b=1) + STREAMING CACHE HINTS: ld.global.cs for the zero-reuse
// read stream, st.global.cs for the zero-reuse write stream, so L2 doesn't
// accumulate ~126MB of dirty output lines and writebacks drain promptly.

#define N_TILES (32 * 256 * 32)

__device__ __forceinline__ float4 ldcs4(const float4* p) {
    float4 v;
    asm volatile("ld.global.cs.v4.f32 {%0,%1,%2,%3}, [%4];"
                 : "=f"(v.x), "=f"(v.y), "=f"(v.z), "=f"(v.w) : "l"(p));
    return v;
}
__device__ __forceinline__ void stcs(float* p, float v) {
    asm volatile("st.global.cs.f32 [%0], %1;" :: "l"(p), "f"(v) : "memory");
}

__device__ __forceinline__ float4 f4add(float4 a, float4 b) {
    return make_float4(a.x + b.x, a.y + b.y, a.z + b.z, a.w + b.w);
}
__device__ __forceinline__ float4 f4max(float4 a, float4 b) {
    return make_float4(fmaxf(a.x, b.x), fmaxf(a.y, b.y),
                       fmaxf(a.z, b.z), fmaxf(a.w, b.w));
}
__device__ __forceinline__ float4 f4shfl_xor(float4 a, int m) {
    float4 r;
    r.x = __shfl_xor_sync(0xffffffffu, a.x, m);
    r.y = __shfl_xor_sync(0xffffffffu, a.y, m);
    r.z = __shfl_xor_sync(0xffffffffu, a.z, m);
    r.w = __shfl_xor_sync(0xffffffffu, a.w, m);
    return r;
}
// token from per-column (sum, max): z_c = sum_c * inv + max_c,
// token = mean_c(z) + max_c(z)
__device__ __forceinline__ float token(float4 s, float4 m, float inv) {
    float zx = fmaf(s.x, inv, m.x);
    float zy = fmaf(s.y, inv, m.y);
    float zz = fmaf(s.z, inv, m.z);
    float zw = fmaf(s.w, inv, m.w);
    float mean = ((zx + zy) + (zz + zw)) * 0.25f;
    float mx = fmaxf(fmaxf(zx, zy), fmaxf(zz, zw));
    return mean + mx;
}

__global__ void __launch_bounds__(256, 6)
hwtp_kernel(const float* __restrict__ x, float* __restrict__ out) {
    int gid  = blockIdx.x * 256 + threadIdx.x;
    int t    = gid & 3;            // width token (4 cols)
    int q    = (gid >> 2) & 3;     // row quarter: rows [4q, 4q+4)
    int tile = gid >> 4;

    // float4 view of the tile: 64 float4; row stride = 4 float4.
    const float4* __restrict__ src =
        reinterpret_cast<const float4*>(x + (size_t)tile * 256) + q * 16 + t;
    float* __restrict__ dst = out + (size_t)tile * 124 + t;

    // ---- Phase 1: all 4 loads up front (streaming, evict-first) ----
    float4 v[4];
#pragma unroll
    for (int r = 0; r < 4; ++r) {
        v[r] = ldcs4(src + r * 4);
    }

    // ---- Phase 2: local pyramid (rows 4q .. 4q+3) ----
    float4 s2s, s2m, s4s, s4m;

#pragma unroll
    for (int r = 0; r < 4; ++r) {
        float4 w = v[r];

        // b=16: single-row bins (global row = 4q + r)
        stcs(dst + (q * 4 + r) * 4, token(w, w, 1.0f));

        if ((r & 1) == 0) {
            s2s = w; s2m = w;
        } else {
            // b=8: 2-row bins (global bin = 2q + (r>>1))
            s2s = f4add(s2s, w);
            s2m = f4max(s2m, w);
            stcs(dst + (16 + q * 2 + (r >> 1)) * 4, token(s2s, s2m, 0.5f));

            if (r == 1) {
                s4s = s2s; s4m = s2m;
            } else {
                // b=4: 4-row bin (global bin = q)
                s4s = f4add(s4s, s2s);
                s4m = f4max(s4m, s2m);
                stcs(dst + (24 + q) * 4, token(s4s, s4m, 0.25f));
            }
        }
    }

    // ---- b=2: combine quarter pairs (q with q^1) via lane^4 ----
    float4 s8s = f4add(s4s, f4shfl_xor(s4s, 4));
    float4 s8m = f4max(s4m, f4shfl_xor(s4m, 4));
    if ((q & 1) == 0) {
        stcs(dst + (28 + (q >> 1)) * 4, token(s8s, s8m, 0.125f));
    }

    // ---- b=1: combine halves (q with q^2) via lane^8 ----
    float4 s16s = f4add(s8s, f4shfl_xor(s8s, 8));
    float4 s16m = f4max(s8m, f4shfl_xor(s8m, 8));
    if (q == 0) {
        stcs(dst + 30 * 4, token(s16s, s16m, 0.0625f));
    }
}

extern "C" void kernel_launch(void* const* d_in, const int* in_sizes, int n_in,
                              void* d_out, int out_size) {
    const float* x = (const float*)d_in[0];
    float* out = (float*)d_out;
    // 262144 tiles * 16 threads = 4,194,304 threads = 16384 blocks of 256 (exact)
    hwtp_kernel<<<(N_TILES * 16) / 256, 256>>>(x, out);
}